// round 17
// baseline (speedup 1.0000x reference)
#include <cuda_runtime.h>
#include <cuda_bf16.h>
#include <cstdint>

#define D 64
#define MAXN 100000

// Scratch accumulator g[N, 64] (static __device__: no allocs allowed)
__device__ __align__(16) float g_scratch[MAXN * D];

// ---------------------------------------------------------------------------
// Scatter:  g[dst[e], :] += (ci[src[e]] * drop_mask[e]) * review_feat[e, :]
// Proven form (~25us, at REDG lane floor): coalesced metadata, ballot skips
// ~70% exact-zero dropout edges, 2 live edges/iter, LDG.128 + red.v4.f32.
// __ldcs on single-use streams keeps g L2-resident for the GEMM (round-16 win).
// ---------------------------------------------------------------------------
__global__ void scatter_kernel(const float4* __restrict__ rf,
                               const float*  __restrict__ ci,
                               const float*  __restrict__ dm,
                               const int*    __restrict__ src,
                               const int*    __restrict__ dst,
                               int E) {
    int warp = (blockIdx.x * blockDim.x + threadIdx.x) >> 5;
    int lane = threadIdx.x & 31;
    int ebase = warp * 32;
    int e = ebase + lane;

    float m = 0.f, s = 0.f;
    int d = 0;
    if (e < E) {
        m = __ldcs(&dm[e]);
        if (m != 0.f) {
            d = __ldcs(&dst[e]);
            s = __ldg(&ci[__ldcs(&src[e])]) * m;
        }
    }
    unsigned mask = __ballot_sync(0xFFFFFFFFu, m != 0.f);

    int half = lane >> 4;
    int q = lane & 15;

    while (mask) {
        int l0 = __ffs(mask) - 1; mask &= mask - 1;
        int l1 = -1;
        if (mask) { l1 = __ffs(mask) - 1; mask &= mask - 1; }

        int l = half ? l1 : l0;
        int lsafe = (l >= 0) ? l : l0;
        float sv = __shfl_sync(0xFFFFFFFFu, s, lsafe);
        int   dv = __shfl_sync(0xFFFFFFFFu, d, lsafe);

        if (l >= 0) {
            float4 v = __ldcs(&rf[(size_t)(ebase + l) * 16 + q]);
            v.x *= sv; v.y *= sv; v.z *= sv; v.w *= sv;
            float* p = &g_scratch[(size_t)dv * D + q * 4];
            asm volatile("red.global.add.v4.f32 [%0], {%1, %2, %3, %4};"
                         :: "l"(p), "f"(v.x), "f"(v.y), "f"(v.z), "f"(v.w)
                         : "memory");
        }
    }
}

// ===========================================================================
// HMMA GEMM: out = (g @ W^T) * ci, fp32 via bf16 Karatsuba 3-pass split.
// PERSISTENT + LEAN-WAVEFRONT variant combining verified pieces:
//  - A fragments loaded DIRECTLY from L2-resident g with LDG.64 (round-14
//    verified layout: rows lane>>2/+8, k (lane&3)*2/+8) -> deletes g staging
//    (LDG+STS) and A-ldsm (~96 L1 wf/warp saved).
//  - B via ldmatrix.x4 (round-13 verified plan: m0/m1 = octet0 k-lo/hi,
//    m2/m3 = octet1 k-lo/hi) -> half the B issue slots.
//  - persistent grid (1 wave, 3 blocks/SM), W converted once per block,
//    __launch_bounds__(256,3).
// Warp tile: 16 rows x 64 cols; block tile 128 rows.
// ===========================================================================
__device__ __forceinline__ uint32_t smem_u32(const void* p) {
    uint32_t a;
    asm("{ .reg .u64 t; cvta.to.shared.u64 t, %1; cvt.u32.u64 %0, t; }"
        : "=r"(a) : "l"(p));
    return a;
}
__device__ __forceinline__ void ldsm_x4(uint32_t& r0, uint32_t& r1,
                                        uint32_t& r2, uint32_t& r3, uint32_t a) {
    asm volatile("ldmatrix.sync.aligned.m8n8.x4.shared.b16 {%0,%1,%2,%3}, [%4];"
                 : "=r"(r0), "=r"(r1), "=r"(r2), "=r"(r3) : "r"(a));
}
__device__ __forceinline__ void mma_bf16(float* d, const uint32_t* a,
                                         uint32_t b0, uint32_t b1) {
    asm volatile("mma.sync.aligned.m16n8k16.row.col.f32.bf16.bf16.f32 "
                 "{%0,%1,%2,%3}, {%4,%5,%6,%7}, {%8,%9}, {%0,%1,%2,%3};"
                 : "+f"(d[0]), "+f"(d[1]), "+f"(d[2]), "+f"(d[3])
                 : "r"(a[0]), "r"(a[1]), "r"(a[2]), "r"(a[3]),
                   "r"(b0), "r"(b1));
}
__device__ __forceinline__ void split2(float2 x, uint32_t& h, uint32_t& l) {
    __nv_bfloat162 h2 = __float22bfloat162_rn(x);
    float2 hf = __bfloat1622float2(h2);
    __nv_bfloat162 l2 = __float22bfloat162_rn(make_float2(x.x - hf.x, x.y - hf.y));
    h = *reinterpret_cast<uint32_t*>(&h2);
    l = *reinterpret_cast<uint32_t*>(&l2);
}
__device__ __forceinline__ void split4w(const float4& x, uint2& hv, uint2& lv) {
    split2(make_float2(x.x, x.y), hv.x, lv.x);
    split2(make_float2(x.z, x.w), hv.y, lv.y);
}

__global__ void __launch_bounds__(256, 3)
gemm_mma_kernel(const float* __restrict__ W, const float* __restrict__ ci,
                float* __restrict__ out, int N, int ntiles) {
    __shared__ __align__(128) char smem[16384];   // WHI [0,8K), WLO [8K,16K)
    uint32_t sb = smem_u32(smem);
    int tid = threadIdx.x, w = tid >> 5, lane = tid & 31;

    // ---- convert W -> bf16 hi/lo, swizzled 16B chunks (once per block) ----
    #pragma unroll
    for (int i = tid; i < 512; i += 256) {
        int f = i >> 3, c = i & 7;
        const float4* wp = reinterpret_cast<const float4*>(W) + f * 16 + c * 2;
        float4 x0 = wp[0], x1 = wp[1];
        uint2 h0, l0, h1, l1;
        split4w(x0, h0, l0);
        split4w(x1, h1, l1);
        uint32_t off = (uint32_t)f * 128 + (uint32_t)((c ^ (f & 7)) << 4);
        *reinterpret_cast<uint4*>(smem + off)        = make_uint4(h0.x, h0.y, h1.x, h1.y);
        *reinterpret_cast<uint4*>(smem + 8192 + off) = make_uint4(l0.x, l0.y, l1.x, l1.y);
    }
    __syncthreads();

    // A fragment coords (round-14 verified)
    int grp = lane >> 2;
    int kin = (lane & 3) * 2;
    // B ldmatrix.x4 lane plan (round-13 verified)
    int bn_off = ((lane >> 4) & 1) * 8 + (lane & 7);
    int bkp = (lane >> 3) & 1;

    for (int tile = blockIdx.x; tile < ntiles; tile += gridDim.x) {
        int row0 = tile * 128;
        int rA = row0 + w * 16 + grp;
        int rB = rA + 8;
        bool okA = rA < N, okB = rB < N;
        const float* gA = &g_scratch[(size_t)rA * D];
        const float* gB = &g_scratch[(size_t)rB * D];

        float acc[8][4];
        #pragma unroll
        for (int nb = 0; nb < 8; nb++)
            #pragma unroll
            for (int j = 0; j < 4; j++) acc[nb][j] = 0.f;

        #pragma unroll
        for (int kc = 0; kc < 4; kc++) {
            // A: 4 LDG.64 from L2-resident g, bf16-split in regs
            int k0 = kc * 16 + kin;
            float2 z = make_float2(0.f, 0.f);
            float2 x00 = okA ? *reinterpret_cast<const float2*>(gA + k0)     : z;
            float2 x10 = okB ? *reinterpret_cast<const float2*>(gB + k0)     : z;
            float2 x01 = okA ? *reinterpret_cast<const float2*>(gA + k0 + 8) : z;
            float2 x11 = okB ? *reinterpret_cast<const float2*>(gB + k0 + 8) : z;
            uint32_t AH[4], AL[4];
            split2(x00, AH[0], AL[0]);
            split2(x10, AH[1], AL[1]);
            split2(x01, AH[2], AL[2]);
            split2(x11, AH[3], AL[3]);

            uint32_t chunk = (uint32_t)(2 * kc + bkp);
            #pragma unroll
            for (int pp = 0; pp < 4; pp++) {     // octet-pairs {0,1},{2,3},{4,5},{6,7}
                int n = pp * 16 + bn_off;
                uint32_t boff = (uint32_t)n * 128 + ((chunk ^ (uint32_t)(n & 7)) << 4);
                uint32_t BH0, BH1, BH2, BH3, BL0, BL1, BL2, BL3;
                ldsm_x4(BH0, BH1, BH2, BH3, sb + boff);
                ldsm_x4(BL0, BL1, BL2, BL3, sb + 8192 + boff);
                mma_bf16(acc[2 * pp],     AH, BH0, BH1);   // hi*hi (octet 2pp)
                mma_bf16(acc[2 * pp + 1], AH, BH2, BH3);   // hi*hi (octet 2pp+1)
                mma_bf16(acc[2 * pp],     AH, BL0, BL1);   // hi*lo
                mma_bf16(acc[2 * pp + 1], AH, BL2, BL3);
                mma_bf16(acc[2 * pp],     AL, BH0, BH1);   // lo*hi
                mma_bf16(acc[2 * pp + 1], AL, BH2, BH3);
            }
        }

        // ---- epilogue: scale by ci[row], float2 stores ----
        int tig = lane & 3;
        float cA = okA ? ci[rA] : 0.f;
        float cB = okB ? ci[rB] : 0.f;
        #pragma unroll
        for (int nb = 0; nb < 8; nb++) {
            int col = nb * 8 + 2 * tig;
            if (okA) {
                float2 v = make_float2(acc[nb][0] * cA, acc[nb][1] * cA);
                *reinterpret_cast<float2*>(&out[(size_t)rA * D + col]) = v;
            }
            if (okB) {
                float2 v = make_float2(acc[nb][2] * cB, acc[nb][3] * cB);
                *reinterpret_cast<float2*>(&out[(size_t)rB * D + col]) = v;
            }
        }
    }
}

// ---------------------------------------------------------------------------
// Launch
// Inputs: review_feat [E,64] f32, ci [N,1] f32, W [64,64] f32,
//         drop_mask [E,1] f32, src [E] i32, dst [E] i32.  Output: [N,64] f32
// ---------------------------------------------------------------------------
extern "C" void kernel_launch(void* const* d_in, const int* in_sizes, int n_in,
                              void* d_out, int out_size) {
    const float4* rf  = (const float4*)d_in[0];
    const float*  ci  = (const float*) d_in[1];
    const float*  W   = (const float*) d_in[2];
    const float*  dm  = (const float*) d_in[3];
    const int*    src = (const int*)   d_in[4];
    const int*    dst = (const int*)   d_in[5];
    float* out = (float*)d_out;

    int E = in_sizes[4];
    int N = in_sizes[1];

    // 1. zero scratch accumulator (graph-capturable memset node)
    void* gptr = nullptr;
    cudaGetSymbolAddress(&gptr, g_scratch);
    cudaMemsetAsync(gptr, 0, (size_t)N * D * sizeof(float), 0);

    // 2. warp-cooperative scatter (streaming hints keep g L2-resident)
    int warps = (E + 31) / 32;
    int sblocks = (warps * 32 + 255) / 256;
    scatter_kernel<<<sblocks, 256>>>(rf, ci, dm, src, dst, E);

    // 3. persistent HMMA GEMM (direct-LDG A, ldsm.x4 B, 3 blocks/SM)
    int ntiles = (N + 127) / 128;
    int grid = 444;                      // 148 SMs x 3 blocks = exactly 1 wave
    if (grid > ntiles) grid = ntiles;
    gemm_mma_kernel<<<grid, 256>>>(W, ci, out, N, ntiles);
}